// round 11
// baseline (speedup 1.0000x reference)
#include <cuda_runtime.h>

// DyDepthwiseConvAtten: B=1024, N=100, C=256, K=3  (rows = 102400)
// Round 11: R10 memory plan (4 rows/warp, coalesced 16B lane stride,
// 16 front-batched streaming LDG.128, invariants amortized 4x) with
// register-pressure fix: the conv output is NOT held across the LN
// butterflies -- it is recomputed from vv4 (3 FMA + 6 SHFL per row) after
// mu/rstd are known. regs <=64 -> 4 CTAs/SM -> smoother DRAM demand.

#define C_DIM 256
#define LN_EPS 1e-5f
#define WARPS_PER_CTA 8
#define RPW 4

__global__ __launch_bounds__(WARPS_PER_CTA * 32, 4)
void dydw_atten_kernel(const float* __restrict__ q,
                       const float* __restrict__ v,
                       const float* __restrict__ Ww,   // [3,256]
                       const float* __restrict__ bw,   // [3]
                       const float* __restrict__ gamma,
                       const float* __restrict__ beta,
                       float* __restrict__ out) {
    const int lane  = threadIdx.x & 31;
    const int wrp   = threadIdx.x >> 5;
    const int gwarp = blockIdx.x * WARPS_PER_CTA + wrp;

    const int c0 = 4 * lane;          // chunk 0: channels [c0, c0+4)
    const int c1 = 128 + 4 * lane;    // chunk 1: channels [c1, c1+4)

    const size_t base0 = (size_t)(gwarp * RPW) * C_DIM;

    // ---- front-batch ALL streaming loads: 16x LDG.128 ----
    float4 qv[RPW][2], vv4[RPW][2];
    #pragma unroll
    for (int r = 0; r < RPW; r++) {
        const size_t b = base0 + (size_t)r * C_DIM;
        qv[r][0]  = __ldcs((const float4*)(q + b + c0));
        qv[r][1]  = __ldcs((const float4*)(q + b + c1));
        vv4[r][0] = __ldcs((const float4*)(v + b + c0));
        vv4[r][1] = __ldcs((const float4*)(v + b + c1));
    }

    // ---- invariants: once per warp, amortized over 4 rows ----
    const float4 w00 = *(const float4*)(Ww + c0);
    const float4 w01 = *(const float4*)(Ww + c1);
    const float4 w10 = *(const float4*)(Ww + C_DIM + c0);
    const float4 w11 = *(const float4*)(Ww + C_DIM + c1);
    const float4 w20 = *(const float4*)(Ww + 2*C_DIM + c0);
    const float4 w21 = *(const float4*)(Ww + 2*C_DIM + c1);
    const float bw0 = bw[0], bw1 = bw[1], bw2 = bw[2];

    // ---- dynamic-weight dots: 12 independent partials, batched butterfly ----
    float p[RPW][3];
    #pragma unroll
    for (int r = 0; r < RPW; r++) {
        const float4 a = qv[r][0], b = qv[r][1];
        p[r][0] = a.x*w00.x + a.y*w00.y + a.z*w00.z + a.w*w00.w
                + b.x*w01.x + b.y*w01.y + b.z*w01.z + b.w*w01.w;
        p[r][1] = a.x*w10.x + a.y*w10.y + a.z*w10.z + a.w*w10.w
                + b.x*w11.x + b.y*w11.y + b.z*w11.z + b.w*w11.w;
        p[r][2] = a.x*w20.x + a.y*w20.y + a.z*w20.z + a.w*w20.w
                + b.x*w21.x + b.y*w21.y + b.z*w21.z + b.w*w21.w;
    }
    #pragma unroll
    for (int off = 16; off > 0; off >>= 1) {
        #pragma unroll
        for (int r = 0; r < RPW; r++) {
            p[r][0] += __shfl_xor_sync(0xffffffffu, p[r][0], off);
            p[r][1] += __shfl_xor_sync(0xffffffffu, p[r][1], off);
            p[r][2] += __shfl_xor_sync(0xffffffffu, p[r][2], off);
        }
    }
    #pragma unroll
    for (int r = 0; r < RPW; r++) {
        p[r][0] += bw0; p[r][1] += bw1; p[r][2] += bw2;   // kw in place
    }

    // ---- pass 1: conv -> LN partial sums (conv output DISCARDED) ----
    float s1[RPW], s2[RPW];
    #pragma unroll
    for (int r = 0; r < RPW; r++) {
        const float4 x0 = vv4[r][0], x1 = vv4[r][1];
        const float chL = __shfl_sync(0xffffffffu, x0.w, 31);   // ch 127
        const float chR = __shfl_sync(0xffffffffu, x1.x, 0);    // ch 128
        float l0 = __shfl_up_sync  (0xffffffffu, x0.w, 1);
        float r0 = __shfl_down_sync(0xffffffffu, x0.x, 1);
        float l1 = __shfl_up_sync  (0xffffffffu, x1.w, 1);
        float r1 = __shfl_down_sync(0xffffffffu, x1.x, 1);
        if (lane == 0)  { l0 = 0.0f; l1 = chL; }
        if (lane == 31) { r0 = chR;  r1 = 0.0f; }

        const float wA[6] = { l0, x0.x, x0.y, x0.z, x0.w, r0 };
        const float wB[6] = { l1, x1.x, x1.y, x1.z, x1.w, r1 };
        float a1 = 0.0f, a2 = 0.0f;
        #pragma unroll
        for (int i = 0; i < 4; i++) {
            const float y0 = wA[i]*p[r][0] + wA[i+1]*p[r][1] + wA[i+2]*p[r][2];
            const float y1 = wB[i]*p[r][0] + wB[i+1]*p[r][1] + wB[i+2]*p[r][2];
            a1 += y0 + y1;
            a2 += y0*y0 + y1*y1;
        }
        s1[r] = a1; s2[r] = a2;
    }

    // ---- LN butterflies: 8 independent chains ----
    #pragma unroll
    for (int off = 16; off > 0; off >>= 1) {
        #pragma unroll
        for (int r = 0; r < RPW; r++) {
            s1[r] += __shfl_xor_sync(0xffffffffu, s1[r], off);
            s2[r] += __shfl_xor_sync(0xffffffffu, s2[r], off);
        }
    }

    // ---- pass 2: recompute conv, normalize, store ----
    const float4 g0  = *(const float4*)(gamma + c0);
    const float4 g1  = *(const float4*)(gamma + c1);
    const float4 bt0 = *(const float4*)(beta  + c0);
    const float4 bt1 = *(const float4*)(beta  + c1);

    #pragma unroll
    for (int r = 0; r < RPW; r++) {
        const float mu   = s1[r] * (1.0f / C_DIM);
        const float rstd = rsqrtf(s2[r] * (1.0f / C_DIM) - mu*mu + LN_EPS);

        const float4 x0 = vv4[r][0], x1 = vv4[r][1];
        const float chL = __shfl_sync(0xffffffffu, x0.w, 31);
        const float chR = __shfl_sync(0xffffffffu, x1.x, 0);
        float l0 = __shfl_up_sync  (0xffffffffu, x0.w, 1);
        float r0 = __shfl_down_sync(0xffffffffu, x0.x, 1);
        float l1 = __shfl_up_sync  (0xffffffffu, x1.w, 1);
        float r1 = __shfl_down_sync(0xffffffffu, x1.x, 1);
        if (lane == 0)  { l0 = 0.0f; l1 = chL; }
        if (lane == 31) { r0 = chR;  r1 = 0.0f; }

        const float wA[6] = { l0, x0.x, x0.y, x0.z, x0.w, r0 };
        const float wB[6] = { l1, x1.x, x1.y, x1.z, x1.w, r1 };
        const float ga[8] = { g0.x, g0.y, g0.z, g0.w, g1.x, g1.y, g1.z, g1.w };
        const float be[8] = { bt0.x, bt0.y, bt0.z, bt0.w, bt1.x, bt1.y, bt1.z, bt1.w };

        float res[8];
        #pragma unroll
        for (int i = 0; i < 4; i++) {
            const float y0 = wA[i]*p[r][0] + wA[i+1]*p[r][1] + wA[i+2]*p[r][2];
            const float y1 = wB[i]*p[r][0] + wB[i+1]*p[r][1] + wB[i+2]*p[r][2];
            res[i]     = (y0 - mu) * rstd * ga[i]     + be[i];
            res[i + 4] = (y1 - mu) * rstd * ga[i + 4] + be[i + 4];
        }
        const size_t b = base0 + (size_t)r * C_DIM;
        __stcs((float4*)(out + b + c0), make_float4(res[0], res[1], res[2], res[3]));
        __stcs((float4*)(out + b + c1), make_float4(res[4], res[5], res[6], res[7]));
    }
}

extern "C" void kernel_launch(void* const* d_in, const int* in_sizes, int n_in,
                              void* d_out, int out_size) {
    const float* q     = (const float*)d_in[0];
    const float* v     = (const float*)d_in[1];
    const float* Ww    = (const float*)d_in[2];
    const float* bw    = (const float*)d_in[3];
    const float* gamma = (const float*)d_in[4];
    const float* beta  = (const float*)d_in[5];
    float* out = (float*)d_out;

    const int rows = out_size / C_DIM;                       // 102400
    const int ctas = rows / (RPW * WARPS_PER_CTA);           // 3200
    dydw_atten_kernel<<<ctas, WARPS_PER_CTA * 32>>>(q, v, Ww, bw, gamma, beta, out);
}